// round 1
// baseline (speedup 1.0000x reference)
#include <cuda_runtime.h>
#include <math.h>

#define HID     256
#define NT      31
#define NTREES  4096
#define NNODES  (NTREES*NT)       // 126976
#define NE_TREE 30
#define NE_HALF (NTREES*NE_TREE)  // 122880
#define VOCAB   780

// ---------------- scratch (static device globals; no allocation) ----------------
__device__ float g_s [NNODES*HID];     // node state s
__device__ float g_rm[NNODES*HID];     // node state rm
__device__ float g_T1[32768*HID];      // Z / R scratch
__device__ float g_T2[32768*HID];      // H scratch
__device__ float g_T3[32768*HID];      // MU scratch (top-down)
__device__ float g_M [32768*HID];      // per-parent M (top-down)
__device__ float g_Pz[VOCAB*HID];      // emb@Wz_x + bz
__device__ float g_Ph[VOCAB*HID];      // emb@Wh_x + bh
__device__ float g_Pr[VOCAB*HID];      // emb@Wr + bu
__device__ float g_Pf[VOCAB*HID];      // emb@Wf_x + bf
__device__ float g_M0 [VOCAB*HID];     // leaf/root message table
__device__ float g_MU0[VOCAB*HID];     // M0 @ Ur

__device__ __forceinline__ float sigf(float x){ return 1.0f/(1.0f+expf(-x)); }

// ------------------------------------------------------------------
// Generic fused GEMM: C[r] = act( A[node(r)] @ W  (+ P[wid[node2(r)]]) (+ bias) )
// A row gather:  node = (r>>aL)*aRS + aBase + (r & ((1<<aL)-1))
// pMode: 0 none, 1 same affine map (pL,pRS,pBase), 2 parent-of-child map
// act: 0 none, 1 sigmoid, 2 tanh, 3 relu
// ------------------------------------------------------------------
__global__ void __launch_bounds__(256) gemm256(
    const float* __restrict__ A, int aL, int aRS, int aBase,
    const float* __restrict__ W,
    float* __restrict__ C, int R, int act,
    const float* __restrict__ P, const int* __restrict__ wid,
    int pMode, int pL, int pRS, int pBase,
    const float* __restrict__ bias)
{
    __shared__ float As[64][65];   // [k][row], padded
    __shared__ float Ws[64][64];   // [k][col]
    const int tid = threadIdx.x;
    const int tx = tid & 15, ty = tid >> 4;
    const int row0 = blockIdx.x * 64, col0 = blockIdx.y * 64;
    const int aMask = (1 << aL) - 1;

    float acc[4][4];
    #pragma unroll
    for (int i = 0; i < 4; i++)
        #pragma unroll
        for (int j = 0; j < 4; j++) acc[i][j] = 0.0f;

    for (int kk = 0; kk < HID; kk += 64) {
        // load A tile (gathered rows), store transposed
        #pragma unroll
        for (int i = 0; i < 4; i++) {
            int r  = ty + i * 16;
            int rg = row0 + r;
            int k4 = tx * 4;
            float4 v = make_float4(0.f, 0.f, 0.f, 0.f);
            if (rg < R) {
                int node = ((rg >> aL) * aRS) + aBase + (rg & aMask);
                v = *(const float4*)(A + (size_t)node * HID + kk + k4);
            }
            As[k4 + 0][r] = v.x; As[k4 + 1][r] = v.y;
            As[k4 + 2][r] = v.z; As[k4 + 3][r] = v.w;
        }
        // load W tile
        #pragma unroll
        for (int i = 0; i < 4; i++) {
            int k = ty + i * 16;
            float4 v = *(const float4*)(W + (size_t)(kk + k) * HID + col0 + tx * 4);
            *(float4*)&Ws[k][tx * 4] = v;
        }
        __syncthreads();

        #pragma unroll 8
        for (int k = 0; k < 64; k++) {
            float a0 = As[k][ty * 4 + 0];
            float a1 = As[k][ty * 4 + 1];
            float a2 = As[k][ty * 4 + 2];
            float a3 = As[k][ty * 4 + 3];
            float4 w = *(const float4*)&Ws[k][tx * 4];
            acc[0][0] += a0 * w.x; acc[0][1] += a0 * w.y; acc[0][2] += a0 * w.z; acc[0][3] += a0 * w.w;
            acc[1][0] += a1 * w.x; acc[1][1] += a1 * w.y; acc[1][2] += a1 * w.z; acc[1][3] += a1 * w.w;
            acc[2][0] += a2 * w.x; acc[2][1] += a2 * w.y; acc[2][2] += a2 * w.z; acc[2][3] += a2 * w.w;
            acc[3][0] += a3 * w.x; acc[3][1] += a3 * w.y; acc[3][2] += a3 * w.z; acc[3][3] += a3 * w.w;
        }
        __syncthreads();
    }

    const int pMask = (1 << pL) - 1;
    #pragma unroll
    for (int i = 0; i < 4; i++) {
        int rg = row0 + ty * 4 + i;
        if (rg >= R) continue;
        const float* prow = nullptr;
        if (pMode == 1) {
            int node2 = ((rg >> pL) * pRS) + pBase + (rg & pMask);
            prow = P + (size_t)wid[node2] * HID;
        } else if (pMode == 2) {
            int tree = rg >> pL;
            int jj   = rg & pMask;
            int pl   = (pBase + jj - 1) >> 1;
            prow = P + (size_t)wid[tree * NT + pl] * HID;
        }
        float* crow = C + (size_t)rg * HID + col0;
        #pragma unroll
        for (int j = 0; j < 4; j++) {
            int c = tx * 4 + j;
            float v = acc[i][j];
            if (prow) v += prow[col0 + c];
            if (bias) v += bias[col0 + c];
            if      (act == 1) v = sigf(v);
            else if (act == 2) v = tanhf(v);
            else if (act == 3) v = fmaxf(v, 0.0f);
            crow[c] = v;
        }
    }
}

// ---------------- elementwise / structural kernels ----------------

__global__ void k_M0() {   // M0[v] = sigmoid(Pz)*tanh(Ph)  (biases baked in)
    size_t o = (size_t)blockIdx.x * HID + threadIdx.x;
    g_M0[o] = sigf(g_Pz[o]) * tanhf(g_Ph[o]);
}

// bottom-up leaf level (d=3): children at depth 4 have zero state -> table path
__global__ void k_bu_leaf(const int* __restrict__ wid, float* __restrict__ out) {
    int p = blockIdx.x, j = threadIdx.x;          // p in [0, 32768)
    int tree = p >> 3, q = p & 7;
    int pl = 7 + q;                               // parent local id (depth 3)
    int parent = tree * NT + pl;
    int c0 = 2 * pl + 1;                          // local child ids c0, c0+1
    int child0 = tree * NT + c0;
    int w0 = wid[child0], w1 = wid[child0 + 1];
    float pr = g_Pr[(size_t)wid[parent] * HID + j];
    float m0 = g_M0[(size_t)w0 * HID + j];
    float m1 = g_M0[(size_t)w1 * HID + j];
    float r0 = sigf(pr + g_MU0[(size_t)w0 * HID + j]);
    float r1 = sigf(pr + g_MU0[(size_t)w1 * HID + j]);
    size_t e0 = (size_t)(tree * NE_TREE + c0 - 1) * HID + j;
    out[e0]       = m0;
    out[e0 + HID] = m1;
    size_t po = (size_t)parent * HID + j;
    g_s[po]  = m0 + m1;
    g_rm[po] = m0 * r0 + m1 * r1;
}

// bottom-up: M = (1-Z)*s + Z*H -> d_out[m_up rows]
__global__ void k_bu_M(int L, int base, float* __restrict__ out) {
    int e = blockIdx.x, j = threadIdx.x;
    int tree = e >> L, jj = e & ((1 << L) - 1);
    int child = tree * NT + base + jj;
    size_t eo = (size_t)e * HID + j;
    float z = g_T1[eo], h = g_T2[eo];
    float s = g_s[(size_t)child * HID + j];
    out[(size_t)(tree * NE_TREE + base - 1 + jj) * HID + j] = (1.0f - z) * s + z * h;
}

// bottom-up: per-parent reduce of its 2 children (m from out, r from T1)
__global__ void k_bu_reduce(int d, int base, const float* __restrict__ out) {
    int p = blockIdx.x, j = threadIdx.x;
    int tree = p >> d, q = p & ((1 << d) - 1);
    int pl = (1 << d) - 1 + q;
    int parent = tree * NT + pl;
    int e0row = tree * (1 << (d + 1)) + 2 * q;
    size_t eid0 = (size_t)(tree * NE_TREE + base - 1 + 2 * q) * HID + j;
    float m0 = out[eid0], m1 = out[eid0 + HID];
    float r0 = g_T1[(size_t)e0row * HID + j];
    float r1 = g_T1[(size_t)(e0row + 1) * HID + j];
    size_t po = (size_t)parent * HID + j;
    g_s[po]  = m0 + m1;
    g_rm[po] = m0 * r0 + m1 * r1;
}

// top-down root level (d=0): zero parent state -> table path
__global__ void k_td_root(const int* __restrict__ wid, float* __restrict__ out) {
    int tree = blockIdx.x, j = threadIdx.x;
    int wr = wid[tree * NT];
    float m  = g_M0 [(size_t)wr * HID + j];
    float mu = g_MU0[(size_t)wr * HID + j];
    #pragma unroll
    for (int c = 1; c <= 2; c++) {
        int child = tree * NT + c;
        float r = sigf(g_Pr[(size_t)wid[child] * HID + j] + mu);
        size_t co = (size_t)child * HID + j;
        g_s[co]  = m;
        g_rm[co] = m * r;
        out[(size_t)(NE_HALF + tree * NE_TREE + c - 1) * HID + j] = m;
    }
}

// top-down: per-parent M = (1-Z)*s+Z*H ; broadcast to both child edge rows of d_out
__global__ void k_td_M(int d, float* __restrict__ out) {
    int p = blockIdx.x, j = threadIdx.x;
    int tree = p >> d, q = p & ((1 << d) - 1);
    int pl = (1 << d) - 1 + q;
    int parent = tree * NT + pl;
    size_t po = (size_t)p * HID + j;
    float z = g_T1[po], h = g_T2[po];
    float s = g_s[(size_t)parent * HID + j];
    float m = (1.0f - z) * s + z * h;
    g_M[po] = m;
    size_t eid0 = (size_t)(NE_HALF + tree * NE_TREE + 2 * pl) * HID + j;
    out[eid0]       = m;
    out[eid0 + HID] = m;
}

// top-down: per-child r; set child states
__global__ void k_td_child(int d, const int* __restrict__ wid) {
    int cr = blockIdx.x, j = threadIdx.x;
    int p = cr >> 1, which = cr & 1;
    int tree = p >> d, q = p & ((1 << d) - 1);
    int pl = (1 << d) - 1 + q;
    int child = tree * NT + 2 * pl + 1 + which;
    size_t po = (size_t)p * HID + j;
    float m = g_M[po];
    float r = sigf(g_Pr[(size_t)wid[child] * HID + j] + g_T3[po]);
    size_t co = (size_t)child * HID + j;
    g_s[co]  = m;
    g_rm[co] = m * r;
}

// ---------------- host-side launch ----------------

static inline void launch_gemm(const float* A, int aL, int aRS, int aBase,
                               const float* W, float* C, int R, int act,
                               const float* P, const int* wid,
                               int pMode, int pL, int pRS, int pBase,
                               const float* bias)
{
    dim3 g((R + 63) / 64, 4);
    gemm256<<<g, 256>>>(A, aL, aRS, aBase, W, C, R, act, P, wid,
                        pMode, pL, pRS, pBase, bias);
}

extern "C" void kernel_launch(void* const* d_in, const int* in_sizes, int n_in,
                              void* d_out, int out_size)
{
    const int*   wid = (const int*)  d_in[0];
    const float* emb = (const float*)d_in[1];
    const float* Wz  = (const float*)d_in[2];
    const float* bz  = (const float*)d_in[3];
    const float* Wh  = (const float*)d_in[4];
    const float* bh  = (const float*)d_in[5];
    const float* Wr  = (const float*)d_in[6];
    const float* Ur  = (const float*)d_in[7];
    const float* bu  = (const float*)d_in[8];
    const float* Wf  = (const float*)d_in[9];
    const float* bf  = (const float*)d_in[10];
    float* out = (float*)d_out;

    const float* Wzs = Wz + 256 * HID;   // state half of Wz
    const float* Whs = Wh + 256 * HID;
    const float* Wfs = Wf + 256 * HID;

    // resolve scratch symbols (host query; capture-safe, deterministic)
    float *p_s, *p_rm, *p_T1, *p_T2, *p_T3, *p_M;
    float *p_Pz, *p_Ph, *p_Pr, *p_Pf, *p_M0, *p_MU0;
    cudaGetSymbolAddress((void**)&p_s,   g_s);
    cudaGetSymbolAddress((void**)&p_rm,  g_rm);
    cudaGetSymbolAddress((void**)&p_T1,  g_T1);
    cudaGetSymbolAddress((void**)&p_T2,  g_T2);
    cudaGetSymbolAddress((void**)&p_T3,  g_T3);
    cudaGetSymbolAddress((void**)&p_M,   g_M);
    cudaGetSymbolAddress((void**)&p_Pz,  g_Pz);
    cudaGetSymbolAddress((void**)&p_Ph,  g_Ph);
    cudaGetSymbolAddress((void**)&p_Pr,  g_Pr);
    cudaGetSymbolAddress((void**)&p_Pf,  g_Pf);
    cudaGetSymbolAddress((void**)&p_M0,  g_M0);
    cudaGetSymbolAddress((void**)&p_MU0, g_MU0);

    // ---- precompute vocab tables (biases baked in) ----
    launch_gemm(emb, 0, 1, 0, Wz, p_Pz, VOCAB, 0, nullptr, nullptr, 0,0,0,0, bz);
    launch_gemm(emb, 0, 1, 0, Wh, p_Ph, VOCAB, 0, nullptr, nullptr, 0,0,0,0, bh);
    launch_gemm(emb, 0, 1, 0, Wr, p_Pr, VOCAB, 0, nullptr, nullptr, 0,0,0,0, bu);
    launch_gemm(emb, 0, 1, 0, Wf, p_Pf, VOCAB, 0, nullptr, nullptr, 0,0,0,0, bf);
    k_M0<<<VOCAB, HID>>>();
    launch_gemm(p_M0, 0, 1, 0, Ur, p_MU0, VOCAB, 0, nullptr, nullptr, 0,0,0,0, nullptr);

    // ---- bottom-up pass ----
    // level d=3: pure table
    k_bu_leaf<<<NTREES * 8, HID>>>(wid, out);
    // levels d=2,1,0
    for (int d = 2; d >= 0; d--) {
        int L = d + 1;
        int base = (1 << (d + 1)) - 1;
        int E = NTREES << (d + 1);
        // Z = sigmoid(Pz[wid_c] + s_c @ Wzs)
        launch_gemm(p_s,  L, NT, base, Wzs, p_T1, E, 1, p_Pz, wid, 1, L, NT, base, nullptr);
        // H = tanh(Ph[wid_c] + rm_c @ Whs)
        launch_gemm(p_rm, L, NT, base, Whs, p_T2, E, 2, p_Ph, wid, 1, L, NT, base, nullptr);
        // M -> d_out (m_up)
        k_bu_M<<<E, HID>>>(L, base, out);
        // R = sigmoid(Pr[wid_parent] + M @ Ur)   (M gathered from d_out edge rows)
        launch_gemm(out, L, NE_TREE, base - 1, Ur, p_T1, E, 1, p_Pr, wid, 2, L, NT, base, nullptr);
        // reduce to parents
        k_bu_reduce<<<E / 2, HID>>>(d, base, out);
    }

    // ---- h_root = relu(Pf[wid_root] + s_root @ Wfs) ----
    launch_gemm(p_s, 0, NT, 0, Wfs, out + (size_t)2 * NE_HALF * HID, NTREES, 3,
                p_Pf, wid, 1, 0, NT, 0, nullptr);

    // ---- top-down pass ----
    // level d=0: pure table
    k_td_root<<<NTREES, HID>>>(wid, out);
    // levels d=1,2,3 (rows = parents at depth d; m shared by both children)
    for (int d = 1; d <= 3; d++) {
        int pbase = (1 << d) - 1;
        int Pn = NTREES << d;
        launch_gemm(p_s,  d, NT, pbase, Wzs, p_T1, Pn, 1, p_Pz, wid, 1, d, NT, pbase, nullptr);
        launch_gemm(p_rm, d, NT, pbase, Whs, p_T2, Pn, 2, p_Ph, wid, 1, d, NT, pbase, nullptr);
        k_td_M<<<Pn, HID>>>(d, out);
        launch_gemm(p_M, 0, 1, 0, Ur, p_T3, Pn, 0, nullptr, nullptr, 0,0,0,0, nullptr);
        k_td_child<<<2 * Pn, HID>>>(d, wid);
    }
}

// round 4
// speedup vs baseline: 1.2071x; 1.2071x over previous
#include <cuda_runtime.h>
#include <cuda_bf16.h>
#include <math.h>
#include <stdint.h>

#define HID     256
#define NT      31
#define NTREES  4096
#define NNODES  (NTREES*NT)       // 126976
#define NE_TREE 30
#define NE_HALF (NTREES*NE_TREE)  // 122880
#define VOCAB   780

// ---------------- scratch (static device globals; no allocation) ----------------
__device__ float g_s [NNODES*HID];
__device__ float g_rm[NNODES*HID];
__device__ float g_T1[32768*HID];
__device__ float g_T2[32768*HID];
__device__ float g_T3[32768*HID];
__device__ float g_M [32768*HID];
__device__ float g_Pz[VOCAB*HID];
__device__ float g_Ph[VOCAB*HID];
__device__ float g_Pr[VOCAB*HID];
__device__ float g_Pf[VOCAB*HID];
__device__ float g_M0 [VOCAB*HID];
__device__ float g_MU0[VOCAB*HID];
__device__ __nv_bfloat16 g_Whi[8*HID*HID];   // transposed [n][k] bf16 hi
__device__ __nv_bfloat16 g_Wlo[8*HID*HID];   // transposed [n][k] bf16 lo

__device__ __forceinline__ float sigf(float x){ return 1.0f/(1.0f+expf(-x)); }

__device__ __forceinline__ uint32_t smem_u32(const void* p){
    uint32_t a;
    asm("{ .reg .u64 t; cvta.to.shared.u64 t, %1; cvt.u32.u64 %0, t; }" : "=r"(a) : "l"(p));
    return a;
}
__device__ __forceinline__ void ldsm_x4(uint32_t a, uint32_t* r){
    asm volatile("ldmatrix.sync.aligned.m8n8.x4.shared.b16 {%0,%1,%2,%3}, [%4];"
        : "=r"(r[0]),"=r"(r[1]),"=r"(r[2]),"=r"(r[3]) : "r"(a));
}
__device__ __forceinline__ void mma_bf16(float* d, const uint32_t* a, const uint32_t* b){
    asm volatile("mma.sync.aligned.m16n8k16.row.col.f32.bf16.bf16.f32 "
        "{%0,%1,%2,%3}, {%4,%5,%6,%7}, {%8,%9}, {%0,%1,%2,%3};"
        : "+f"(d[0]),"+f"(d[1]),"+f"(d[2]),"+f"(d[3])
        : "r"(a[0]),"r"(a[1]),"r"(a[2]),"r"(a[3]), "r"(b[0]),"r"(b[1]));
}
#define SWZ(o) ((o) ^ (((o) >> 3) & 0x70))

// SMEM: AH [0,16K) AL [16K,32K) WH [32K,48K) WL [48K,64K)
#define SMEM_SZ 65536

// ------------------------------------------------------------------
// Tensor-core GEMM (bf16-split, fp32 accum), semantics identical to the
// round-1 fp32 gemm256:
//   C[rg, col] = act( A[node(rg)] @ W  (+ P[wid[node2(rg)]]) (+ bias) )
//   node = (rg>>aL)*aRS + aBase + (rg & ((1<<aL)-1))
//   pMode: 0 none, 1 same affine map, 2 parent-of-child map
//   act: 0 none, 1 sigmoid, 2 tanh, 3 relu
// Block: 128 rows x 128 cols (grid.y=2), 256 threads (8 warps, 4x2).
// ------------------------------------------------------------------
__global__ void __launch_bounds__(256,1) gemm_mma(
    const float* __restrict__ A, int aL, int aRS, int aBase,
    const __nv_bfloat16* __restrict__ WHI, const __nv_bfloat16* __restrict__ WLO,
    float* __restrict__ C, int R, int act,
    const float* __restrict__ P, const int* __restrict__ wid,
    int pMode, int pL, int pRS, int pBase,
    const float* __restrict__ bias)
{
    extern __shared__ char smc[];
    const uint32_t sb = smem_u32(smc);
    const int tid = threadIdx.x, l = tid & 31, w = tid >> 5;
    const int wm = w >> 1, wn = w & 1;
    const int row0 = blockIdx.x * 128, col0 = blockIdx.y * 128;
    const int aMask = (1 << aL) - 1;

    // A gather source for loading (2 threads per row)
    const int ar = tid >> 1, ah = tid & 1;
    const int arg = row0 + ar;
    const float* Arow = nullptr;
    if (arg < R) {
        int an = ((arg >> aL) * aRS) + aBase + (arg & aMask);
        Arow = A + (size_t)an * HID;
    }
    const __nv_bfloat16* WHrow = WHI + (size_t)(col0 + ar) * HID + ah * 32;
    const __nv_bfloat16* WLrow = WLO + (size_t)(col0 + ar) * HID + ah * 32;

    float acc[2][8][4];
    #pragma unroll
    for (int i = 0; i < 2; i++)
        #pragma unroll
        for (int j = 0; j < 8; j++)
            #pragma unroll
            for (int q = 0; q < 4; q++) acc[i][j][q] = 0.0f;

    for (int kc = 0; kc < 4; kc++) {
        // ---- stage A chunk: 128 rows x 64 k, fp32 -> bf16 hi/lo, SW128 ----
        #pragma unroll
        for (int i = 0; i < 8; i++) {
            float4 v = Arow ? *(const float4*)(Arow + kc*64 + ah*32 + i*4)
                            : make_float4(0.f,0.f,0.f,0.f);
            __nv_bfloat162 h01 = __floats2bfloat162_rn(v.x, v.y);
            __nv_bfloat162 h23 = __floats2bfloat162_rn(v.z, v.w);
            float lx = v.x - __bfloat162float(h01.x);
            float ly = v.y - __bfloat162float(h01.y);
            float lz = v.z - __bfloat162float(h23.x);
            float lw = v.w - __bfloat162float(h23.y);
            __nv_bfloat162 l01 = __floats2bfloat162_rn(lx, ly);
            __nv_bfloat162 l23 = __floats2bfloat162_rn(lz, lw);
            uint32_t so = SWZ((uint32_t)(ar*128 + ah*64 + i*8));
            *(uint2*)(smc +         so) = make_uint2(*(uint32_t*)&h01, *(uint32_t*)&h23);
            *(uint2*)(smc + 16384 + so) = make_uint2(*(uint32_t*)&l01, *(uint32_t*)&l23);
        }
        // ---- stage W chunk: 128 n-rows x 64 k bf16 (pre-transposed), SW128 ----
        #pragma unroll
        for (int i = 0; i < 4; i++) {
            uint32_t so = SWZ((uint32_t)(ar*128 + ah*64 + i*16));
            *(uint4*)(smc + 32768 + so) = *(const uint4*)(WHrow + kc*64 + i*8);
            *(uint4*)(smc + 49152 + so) = *(const uint4*)(WLrow + kc*64 + i*8);
        }
        __syncthreads();

        #pragma unroll
        for (int ks = 0; ks < 4; ks++) {
            uint32_t fah[2][4], fal[2][4], fbh[8][2], fbl[8][2];
            #pragma unroll
            for (int ms = 0; ms < 2; ms++) {
                int rrow = wm*32 + ms*16 + (l & 15);
                int kb   = ks*16 + (l >> 4) * 8;
                uint32_t off = SWZ((uint32_t)(rrow*128 + kb*2));
                ldsm_x4(sb +         off, fah[ms]);
                ldsm_x4(sb + 16384 + off, fal[ms]);
            }
            #pragma unroll
            for (int p = 0; p < 4; p++) {
                int mi   = l >> 3;
                int nrow = wn*64 + p*16 + (mi >> 1) * 8 + (l & 7);
                int kb   = ks*16 + (mi & 1) * 8;
                uint32_t off = SWZ((uint32_t)(nrow*128 + kb*2));
                uint32_t r[4];
                ldsm_x4(sb + 32768 + off, r);
                fbh[2*p][0] = r[0]; fbh[2*p][1] = r[1];
                fbh[2*p+1][0] = r[2]; fbh[2*p+1][1] = r[3];
                ldsm_x4(sb + 49152 + off, r);
                fbl[2*p][0] = r[0]; fbl[2*p][1] = r[1];
                fbl[2*p+1][0] = r[2]; fbl[2*p+1][1] = r[3];
            }
            #pragma unroll
            for (int ms = 0; ms < 2; ms++)
                #pragma unroll
                for (int ns = 0; ns < 8; ns++) {
                    mma_bf16(acc[ms][ns], fah[ms], fbh[ns]);
                    mma_bf16(acc[ms][ns], fah[ms], fbl[ns]);
                    mma_bf16(acc[ms][ns], fal[ms], fbh[ns]);
                }
        }
        __syncthreads();
    }

    // ---------------- fused epilogue ----------------
    const int pMask = (1 << pL) - 1;
    #pragma unroll
    for (int ms = 0; ms < 2; ms++) {
        #pragma unroll
        for (int rr = 0; rr < 2; rr++) {
            int rg = row0 + wm*32 + ms*16 + (l >> 2) + rr*8;
            if (rg >= R) continue;
            const float* prow = nullptr;
            if (pMode == 1) {
                int n2 = ((rg >> pL) * pRS) + pBase + (rg & pMask);
                prow = P + (size_t)wid[n2] * HID;
            } else if (pMode == 2) {
                int tree = rg >> pL;
                int jj   = rg & pMask;
                int pl2  = (pBase + jj - 1) >> 1;
                prow = P + (size_t)wid[tree * NT + pl2] * HID;
            }
            float* crow = C + (size_t)rg * HID;
            #pragma unroll
            for (int ns = 0; ns < 8; ns++) {
                int c = col0 + wn*64 + ns*8 + (l & 3) * 2;
                float v0 = acc[ms][ns][rr*2 + 0];
                float v1 = acc[ms][ns][rr*2 + 1];
                if (prow) { v0 += prow[c]; v1 += prow[c+1]; }
                if (bias) { v0 += bias[c]; v1 += bias[c+1]; }
                if      (act == 1) { v0 = sigf(v0);       v1 = sigf(v1); }
                else if (act == 2) { v0 = tanhf(v0);      v1 = tanhf(v1); }
                else if (act == 3) { v0 = fmaxf(v0, 0.f); v1 = fmaxf(v1, 0.f); }
                *(float2*)(crow + c) = make_float2(v0, v1);
            }
        }
    }
}

// ---------------- weight transpose + bf16 split prep ----------------
__global__ void k_prepw(const float* __restrict__ Wz, const float* __restrict__ Wh,
                        const float* __restrict__ Wr, const float* __restrict__ Ur,
                        const float* __restrict__ Wf)
{
    const float* src;
    switch (blockIdx.x) {
        case 0: src = Wz; break;            case 1: src = Wz + 256*HID; break;
        case 2: src = Wh; break;            case 3: src = Wh + 256*HID; break;
        case 4: src = Wr; break;            case 5: src = Ur; break;
        case 6: src = Wf; break;            default: src = Wf + 256*HID; break;
    }
    int n = threadIdx.x;
    size_t mb = (size_t)blockIdx.x * HID * HID;
    int k0 = blockIdx.y * 32;
    for (int k = k0; k < k0 + 32; k++) {
        float v = src[(size_t)k * HID + n];
        __nv_bfloat16 h = __float2bfloat16(v);
        float lo = v - __bfloat162float(h);
        g_Whi[mb + (size_t)n * HID + k] = h;
        g_Wlo[mb + (size_t)n * HID + k] = __float2bfloat16(lo);
    }
}

// ---------------- elementwise / structural kernels (proven in round 1) ----------------
__global__ void k_M0() {
    size_t o = (size_t)blockIdx.x * HID + threadIdx.x;
    g_M0[o] = sigf(g_Pz[o]) * tanhf(g_Ph[o]);
}

__global__ void k_bu_leaf(const int* __restrict__ wid, float* __restrict__ out) {
    int p = blockIdx.x, j = threadIdx.x;
    int tree = p >> 3, q = p & 7;
    int pl = 7 + q;
    int parent = tree * NT + pl;
    int c0 = 2 * pl + 1;
    int child0 = tree * NT + c0;
    int w0 = wid[child0], w1 = wid[child0 + 1];
    float pr = g_Pr[(size_t)wid[parent] * HID + j];
    float m0 = g_M0[(size_t)w0 * HID + j];
    float m1 = g_M0[(size_t)w1 * HID + j];
    float r0 = sigf(pr + g_MU0[(size_t)w0 * HID + j]);
    float r1 = sigf(pr + g_MU0[(size_t)w1 * HID + j]);
    size_t e0 = (size_t)(tree * NE_TREE + c0 - 1) * HID + j;
    out[e0]       = m0;
    out[e0 + HID] = m1;
    size_t po = (size_t)parent * HID + j;
    g_s[po]  = m0 + m1;
    g_rm[po] = m0 * r0 + m1 * r1;
}

__global__ void k_bu_M(int L, int base, float* __restrict__ out) {
    int e = blockIdx.x, j = threadIdx.x;
    int tree = e >> L, jj = e & ((1 << L) - 1);
    int child = tree * NT + base + jj;
    size_t eo = (size_t)e * HID + j;
    float z = g_T1[eo], h = g_T2[eo];
    float s = g_s[(size_t)child * HID + j];
    out[(size_t)(tree * NE_TREE + base - 1 + jj) * HID + j] = (1.0f - z) * s + z * h;
}

__global__ void k_bu_reduce(int d, int base, const float* __restrict__ out) {
    int p = blockIdx.x, j = threadIdx.x;
    int tree = p >> d, q = p & ((1 << d) - 1);
    int pl = (1 << d) - 1 + q;
    int parent = tree * NT + pl;
    int e0row = tree * (1 << (d + 1)) + 2 * q;
    size_t eid0 = (size_t)(tree * NE_TREE + base - 1 + 2 * q) * HID + j;
    float m0 = out[eid0], m1 = out[eid0 + HID];
    float r0 = g_T1[(size_t)e0row * HID + j];
    float r1 = g_T1[(size_t)(e0row + 1) * HID + j];
    size_t po = (size_t)parent * HID + j;
    g_s[po]  = m0 + m1;
    g_rm[po] = m0 * r0 + m1 * r1;
}

__global__ void k_td_root(const int* __restrict__ wid, float* __restrict__ out) {
    int tree = blockIdx.x, j = threadIdx.x;
    int wr = wid[tree * NT];
    float m  = g_M0 [(size_t)wr * HID + j];
    float mu = g_MU0[(size_t)wr * HID + j];
    #pragma unroll
    for (int c = 1; c <= 2; c++) {
        int child = tree * NT + c;
        float r = sigf(g_Pr[(size_t)wid[child] * HID + j] + mu);
        size_t co = (size_t)child * HID + j;
        g_s[co]  = m;
        g_rm[co] = m * r;
        out[(size_t)(NE_HALF + tree * NE_TREE + c - 1) * HID + j] = m;
    }
}

__global__ void k_td_M(int d, float* __restrict__ out) {
    int p = blockIdx.x, j = threadIdx.x;
    int tree = p >> d, q = p & ((1 << d) - 1);
    int pl = (1 << d) - 1 + q;
    int parent = tree * NT + pl;
    size_t po = (size_t)p * HID + j;
    float z = g_T1[po], h = g_T2[po];
    float s = g_s[(size_t)parent * HID + j];
    float m = (1.0f - z) * s + z * h;
    g_M[po] = m;
    size_t eid0 = (size_t)(NE_HALF + tree * NE_TREE + 2 * pl) * HID + j;
    out[eid0]       = m;
    out[eid0 + HID] = m;
}

__global__ void k_td_child(int d, const int* __restrict__ wid) {
    int cr = blockIdx.x, j = threadIdx.x;
    int p = cr >> 1, which = cr & 1;
    int tree = p >> d, q = p & ((1 << d) - 1);
    int pl = (1 << d) - 1 + q;
    int child = tree * NT + 2 * pl + 1 + which;
    size_t po = (size_t)p * HID + j;
    float m = g_M[po];
    float r = sigf(g_Pr[(size_t)wid[child] * HID + j] + g_T3[po]);
    size_t co = (size_t)child * HID + j;
    g_s[co]  = m;
    g_rm[co] = m * r;
}

// ---------------- host ----------------
static __nv_bfloat16 *hp_Whi, *hp_Wlo;

static inline void tc(const float* A, int aL, int aRS, int aBase, int mat,
                      float* C, int R, int act,
                      const float* P, const int* wid,
                      int pMode, int pL, int pRS, int pBase,
                      const float* bias)
{
    dim3 g((R + 127) / 128, 2);
    gemm_mma<<<g, 256, SMEM_SZ>>>(
        A, aL, aRS, aBase,
        hp_Whi + (size_t)mat * HID * HID, hp_Wlo + (size_t)mat * HID * HID,
        C, R, act, P, wid, pMode, pL, pRS, pBase, bias);
}

extern "C" void kernel_launch(void* const* d_in, const int* in_sizes, int n_in,
                              void* d_out, int out_size)
{
    const int*   wid = (const int*)  d_in[0];
    const float* emb = (const float*)d_in[1];
    const float* Wz  = (const float*)d_in[2];
    const float* bz  = (const float*)d_in[3];
    const float* Wh  = (const float*)d_in[4];
    const float* bh  = (const float*)d_in[5];
    const float* Wr  = (const float*)d_in[6];
    const float* Ur  = (const float*)d_in[7];
    const float* bu  = (const float*)d_in[8];
    const float* Wf  = (const float*)d_in[9];
    const float* bf  = (const float*)d_in[10];
    float* out = (float*)d_out;

    float *p_s, *p_rm, *p_T1, *p_T3, *p_M;
    float *p_Pz, *p_Ph, *p_Pr, *p_Pf, *p_M0, *p_MU0;
    cudaGetSymbolAddress((void**)&p_s,   g_s);
    cudaGetSymbolAddress((void**)&p_rm,  g_rm);
    cudaGetSymbolAddress((void**)&p_T1,  g_T1);
    float* p_T2; cudaGetSymbolAddress((void**)&p_T2, g_T2);
    cudaGetSymbolAddress((void**)&p_T3,  g_T3);
    cudaGetSymbolAddress((void**)&p_M,   g_M);
    cudaGetSymbolAddress((void**)&p_Pz,  g_Pz);
    cudaGetSymbolAddress((void**)&p_Ph,  g_Ph);
    cudaGetSymbolAddress((void**)&p_Pr,  g_Pr);
    cudaGetSymbolAddress((void**)&p_Pf,  g_Pf);
    cudaGetSymbolAddress((void**)&p_M0,  g_M0);
    cudaGetSymbolAddress((void**)&p_MU0, g_MU0);
    cudaGetSymbolAddress((void**)&hp_Whi, g_Whi);
    cudaGetSymbolAddress((void**)&hp_Wlo, g_Wlo);

    cudaFuncSetAttribute(gemm_mma, cudaFuncAttributeMaxDynamicSharedMemorySize, SMEM_SZ);

    // ---- weight prep (transpose + bf16 split) ----
    k_prepw<<<dim3(8, 8), 256>>>(Wz, Wh, Wr, Ur, Wf);

    // ---- vocab tables (biases baked in) ----
    tc(emb,  0, 1, 0, 0, p_Pz, VOCAB, 0, nullptr, nullptr, 0,0,0,0, bz);
    tc(emb,  0, 1, 0, 2, p_Ph, VOCAB, 0, nullptr, nullptr, 0,0,0,0, bh);
    tc(emb,  0, 1, 0, 4, p_Pr, VOCAB, 0, nullptr, nullptr, 0,0,0,0, bu);
    tc(emb,  0, 1, 0, 6, p_Pf, VOCAB, 0, nullptr, nullptr, 0,0,0,0, bf);
    k_M0<<<VOCAB, HID>>>();
    tc(p_M0, 0, 1, 0, 5, p_MU0, VOCAB, 0, nullptr, nullptr, 0,0,0,0, nullptr);

    // ---- bottom-up pass ----
    k_bu_leaf<<<NTREES * 8, HID>>>(wid, out);
    for (int d = 2; d >= 0; d--) {
        int L = d + 1;
        int base = (1 << (d + 1)) - 1;
        int E = NTREES << (d + 1);
        // Z = sigmoid(Pz[wid_c] + s_c @ Wzs)
        tc(p_s,  L, NT, base, 1, p_T1, E, 1, p_Pz, wid, 1, L, NT, base, nullptr);
        // H = tanh(Ph[wid_c] + rm_c @ Whs)
        tc(p_rm, L, NT, base, 3, p_T2, E, 2, p_Ph, wid, 1, L, NT, base, nullptr);
        // M -> d_out (m_up)
        k_bu_M<<<E, HID>>>(L, base, out);
        // R = sigmoid(Pr[wid_parent] + M @ Ur)
        tc(out,  L, NE_TREE, base - 1, 5, p_T1, E, 1, p_Pr, wid, 2, L, NT, base, nullptr);
        k_bu_reduce<<<E / 2, HID>>>(d, base, out);
    }

    // ---- h_root = relu(Pf[wid_root] + s_root @ Wfs) ----
    tc(p_s, 0, NT, 0, 7, out + (size_t)2 * NE_HALF * HID, NTREES, 3,
       p_Pf, wid, 1, 0, NT, 0, nullptr);

    // ---- top-down pass ----
    k_td_root<<<NTREES, HID>>>(wid, out);
    for (int d = 1; d <= 3; d++) {
        int pb = (1 << d) - 1;
        int Pn = NTREES << d;
        tc(p_s,  d, NT, pb, 1, p_T1, Pn, 1, p_Pz, wid, 1, d, NT, pb, nullptr);
        tc(p_rm, d, NT, pb, 3, p_T2, Pn, 2, p_Ph, wid, 1, d, NT, pb, nullptr);
        k_td_M<<<Pn, HID>>>(d, out);
        tc(p_M,  0, 1, 0, 5, p_T3, Pn, 0, nullptr, nullptr, 0,0,0,0, nullptr);
        k_td_child<<<2 * Pn, HID>>>(d, wid);
    }
}

// round 5
// speedup vs baseline: 1.2927x; 1.0709x over previous
#include <cuda_runtime.h>
#include <cuda_bf16.h>
#include <math.h>
#include <stdint.h>

#define HID     256
#define NT      31
#define NTREES  4096
#define NNODES  (NTREES*NT)       // 126976
#define NE_TREE 30
#define NE_HALF (NTREES*NE_TREE)  // 122880
#define VOCAB   780

// ---------------- scratch (static device globals; no allocation) ----------------
__device__ float g_s [NNODES*HID];
__device__ float g_rm[NNODES*HID];
__device__ float g_T1[32768*HID];
__device__ float g_T2[32768*HID];
__device__ float g_T3[32768*HID];
__device__ float g_M [32768*HID];
__device__ float g_Pz[VOCAB*HID];
__device__ float g_Ph[VOCAB*HID];
__device__ float g_Pr[VOCAB*HID];
__device__ float g_Pf[VOCAB*HID];
__device__ float g_M0 [VOCAB*HID];
__device__ float g_MU0[VOCAB*HID];
__device__ __nv_bfloat16 g_Whi[8*HID*HID];   // transposed [n][k] bf16 hi
__device__ __nv_bfloat16 g_Wlo[8*HID*HID];   // transposed [n][k] bf16 lo

__device__ __forceinline__ float sigf(float x){ return 1.0f/(1.0f+expf(-x)); }

__device__ __forceinline__ uint32_t smem_u32(const void* p){
    uint32_t a;
    asm("{ .reg .u64 t; cvta.to.shared.u64 t, %1; cvt.u32.u64 %0, t; }" : "=r"(a) : "l"(p));
    return a;
}
__device__ __forceinline__ void ldsm_x4(uint32_t a, uint32_t* r){
    asm volatile("ldmatrix.sync.aligned.m8n8.x4.shared.b16 {%0,%1,%2,%3}, [%4];"
        : "=r"(r[0]),"=r"(r[1]),"=r"(r[2]),"=r"(r[3]) : "r"(a));
}
__device__ __forceinline__ void mma_bf16(float* d, const uint32_t* a, const uint32_t* b){
    asm volatile("mma.sync.aligned.m16n8k16.row.col.f32.bf16.bf16.f32 "
        "{%0,%1,%2,%3}, {%4,%5,%6,%7}, {%8,%9}, {%0,%1,%2,%3};"
        : "+f"(d[0]),"+f"(d[1]),"+f"(d[2]),"+f"(d[3])
        : "r"(a[0]),"r"(a[1]),"r"(a[2]),"r"(a[3]), "r"(b[0]),"r"(b[1]));
}
__device__ __forceinline__ void cp16(uint32_t dst, const void* src){
    asm volatile("cp.async.cg.shared.global [%0], [%1], 16;" :: "r"(dst), "l"(src));
}
#define CP_COMMIT() asm volatile("cp.async.commit_group;" ::: "memory")
#define CP_WAIT0()  asm volatile("cp.async.wait_group 0;" ::: "memory")

#define SWZ(o) ((o) ^ (((o) >> 3) & 0x70))

// per stage: AH[0,16K) AL[16K,32K) WH[32K,48K) WL[48K,64K); 2 stages
#define STAGE (65536)
#define SMEM_TOT (2*STAGE)

struct GJob {
    const float* A;       // gathered A source
    float*       C;       // output
    const float* P;       // vocab table (optional)
    const float* bias;    // bias (optional)
    int mat;              // weight matrix index into g_Whi/g_Wlo
    int act;              // 0 none, 1 sigmoid, 2 tanh, 3 relu
};

// ------------------------------------------------------------------
// Pipelined tensor-core GEMM (bf16-split, fp32 accum).
//   C[rg, col] = act( A[node(rg)] @ W  (+ P[wid[node2(rg)]]) (+ bias) )
//   node = (rg>>aL)*aRS + aBase + (rg & ((1<<aL)-1))
//   pMode: 0 none, 1 same affine map, 2 parent-of-child map
// grid: (ceil(R/128), 2, nJobs); block 256 (8 warps, 4x2).
// ------------------------------------------------------------------
__global__ void __launch_bounds__(256,1) gemm_mma(
    GJob j0, GJob j1, GJob j2, GJob j3,
    int aL, int aRS, int aBase, int R,
    const int* __restrict__ wid,
    int pMode, int pL, int pRS, int pBase)
{
    extern __shared__ char smc[];
    const uint32_t sb = smem_u32(smc);
    const int tid = threadIdx.x, l = tid & 31, w = tid >> 5;
    const int wm = w >> 1, wn = w & 1;
    const int row0 = blockIdx.x * 128, col0 = blockIdx.y * 128;
    const int aMask = (1 << aL) - 1;

    const GJob j = (blockIdx.z == 0) ? j0 : (blockIdx.z == 1) ? j1
                 : (blockIdx.z == 2) ? j2 : j3;

    // A gather (2 threads per row)
    const int ar = tid >> 1, ah = tid & 1;
    const int arg = row0 + ar;
    const float* Arow = nullptr;
    if (arg < R) {
        int an = ((arg >> aL) * aRS) + aBase + (arg & aMask);
        Arow = j.A + (size_t)an * HID;
    }
    const __nv_bfloat16* WHrow = g_Whi + (size_t)j.mat * HID * HID + (size_t)(col0 + ar) * HID + ah * 32;
    const __nv_bfloat16* WLrow = g_Wlo + (size_t)j.mat * HID * HID + (size_t)(col0 + ar) * HID + ah * 32;

    float acc[2][8][4];
    #pragma unroll
    for (int i = 0; i < 2; i++)
        #pragma unroll
        for (int jj = 0; jj < 8; jj++)
            #pragma unroll
            for (int q = 0; q < 4; q++) acc[i][jj][q] = 0.0f;

    // stage offsets
    const uint32_t aso = SWZ((uint32_t)(ar*128 + ah*64));   // base within A part (add i*8*... below)
    (void)aso;

    // ---- helpers as macros ----
    float4 av[8];
#define LOAD_A_REGS(kc) do { \
    _Pragma("unroll") \
    for (int i = 0; i < 8; i++) \
        av[i] = Arow ? *(const float4*)(Arow + (kc)*64 + ah*32 + i*4) \
                     : make_float4(0.f,0.f,0.f,0.f); \
} while(0)

#define STS_A(st) do { \
    char* bp = smc + (st)*STAGE; \
    _Pragma("unroll") \
    for (int i = 0; i < 8; i++) { \
        float4 v = av[i]; \
        __nv_bfloat162 h01 = __floats2bfloat162_rn(v.x, v.y); \
        __nv_bfloat162 h23 = __floats2bfloat162_rn(v.z, v.w); \
        float lx = v.x - __bfloat162float(h01.x); \
        float ly = v.y - __bfloat162float(h01.y); \
        float lz = v.z - __bfloat162float(h23.x); \
        float lw = v.w - __bfloat162float(h23.y); \
        __nv_bfloat162 l01 = __floats2bfloat162_rn(lx, ly); \
        __nv_bfloat162 l23 = __floats2bfloat162_rn(lz, lw); \
        uint32_t so = SWZ((uint32_t)(ar*128 + ah*64 + i*8)); \
        *(uint2*)(bp +         so) = make_uint2(*(uint32_t*)&h01, *(uint32_t*)&h23); \
        *(uint2*)(bp + 16384 + so) = make_uint2(*(uint32_t*)&l01, *(uint32_t*)&l23); \
    } \
} while(0)

#define CP_W(st, kc) do { \
    uint32_t bb = sb + (st)*STAGE; \
    _Pragma("unroll") \
    for (int i = 0; i < 4; i++) { \
        uint32_t so = SWZ((uint32_t)(ar*128 + ah*64 + i*16)); \
        cp16(bb + 32768 + so, WHrow + (kc)*64 + i*8); \
        cp16(bb + 49152 + so, WLrow + (kc)*64 + i*8); \
    } \
} while(0)

    // ---- prologue: chunk 0 ----
    LOAD_A_REGS(0);
    CP_W(0, 0);
    CP_COMMIT();
    STS_A(0);
    CP_WAIT0();
    __syncthreads();

    for (int kc = 0; kc < 4; kc++) {
        const int st = kc & 1;
        if (kc < 3) {
            CP_W(st ^ 1, kc + 1);
            CP_COMMIT();
            LOAD_A_REGS(kc + 1);
        }
        // ---- compute chunk kc from stage st ----
        {
            const uint32_t sb2 = sb + st * STAGE;
            #pragma unroll
            for (int ks = 0; ks < 4; ks++) {
                uint32_t fah[2][4], fal[2][4];
                #pragma unroll
                for (int ms = 0; ms < 2; ms++) {
                    int rrow = wm*32 + ms*16 + (l & 15);
                    int kb   = ks*16 + (l >> 4) * 8;
                    uint32_t off = SWZ((uint32_t)(rrow*128 + kb*2));
                    ldsm_x4(sb2 +         off, fah[ms]);
                    ldsm_x4(sb2 + 16384 + off, fal[ms]);
                }
                #pragma unroll
                for (int p = 0; p < 4; p++) {
                    int mi   = l >> 3;
                    int nrow = wn*64 + p*16 + (mi >> 1) * 8 + (l & 7);
                    int kb   = ks*16 + (mi & 1) * 8;
                    uint32_t off = SWZ((uint32_t)(nrow*128 + kb*2));
                    uint32_t rh[4], rl[4];
                    ldsm_x4(sb2 + 32768 + off, rh);
                    ldsm_x4(sb2 + 49152 + off, rl);
                    #pragma unroll
                    for (int ms = 0; ms < 2; ms++) {
                        mma_bf16(acc[ms][2*p],   fah[ms], &rh[0]);
                        mma_bf16(acc[ms][2*p],   fah[ms], &rl[0]);
                        mma_bf16(acc[ms][2*p],   fal[ms], &rh[0]);
                        mma_bf16(acc[ms][2*p+1], fah[ms], &rh[2]);
                        mma_bf16(acc[ms][2*p+1], fah[ms], &rl[2]);
                        mma_bf16(acc[ms][2*p+1], fal[ms], &rh[2]);
                    }
                }
            }
        }
        if (kc < 3) {
            STS_A(st ^ 1);
            CP_WAIT0();
        }
        __syncthreads();
    }

    // ---------------- fused epilogue ----------------
    const int pMask = (1 << pL) - 1;
    #pragma unroll
    for (int ms = 0; ms < 2; ms++) {
        #pragma unroll
        for (int rr = 0; rr < 2; rr++) {
            int rg = row0 + wm*32 + ms*16 + (l >> 2) + rr*8;
            if (rg >= R) continue;
            const float* prow = nullptr;
            if (pMode == 1) {
                int n2 = ((rg >> pL) * pRS) + pBase + (rg & pMask);
                prow = j.P + (size_t)wid[n2] * HID;
            } else if (pMode == 2) {
                int tree = rg >> pL;
                int jj2  = rg & pMask;
                int pl2  = (pBase + jj2 - 1) >> 1;
                prow = j.P + (size_t)wid[tree * NT + pl2] * HID;
            }
            float* crow = j.C + (size_t)rg * HID;
            #pragma unroll
            for (int ns = 0; ns < 8; ns++) {
                int c = col0 + wn*64 + ns*8 + (l & 3) * 2;
                float v0 = acc[ms][ns][rr*2 + 0];
                float v1 = acc[ms][ns][rr*2 + 1];
                if (prow)  { v0 += prow[c];  v1 += prow[c+1]; }
                if (j.bias){ v0 += j.bias[c]; v1 += j.bias[c+1]; }
                if      (j.act == 1) { v0 = sigf(v0);       v1 = sigf(v1); }
                else if (j.act == 2) { v0 = tanhf(v0);      v1 = tanhf(v1); }
                else if (j.act == 3) { v0 = fmaxf(v0, 0.f); v1 = fmaxf(v1, 0.f); }
                *(float2*)(crow + c) = make_float2(v0, v1);
            }
        }
    }
#undef LOAD_A_REGS
#undef STS_A
#undef CP_W
}

// ---------------- weight transpose + bf16 split prep ----------------
__global__ void k_prepw(const float* __restrict__ Wz, const float* __restrict__ Wh,
                        const float* __restrict__ Wr, const float* __restrict__ Ur,
                        const float* __restrict__ Wf)
{
    const float* src;
    switch (blockIdx.x) {
        case 0: src = Wz; break;            case 1: src = Wz + 256*HID; break;
        case 2: src = Wh; break;            case 3: src = Wh + 256*HID; break;
        case 4: src = Wr; break;            case 5: src = Ur; break;
        case 6: src = Wf; break;            default: src = Wf + 256*HID; break;
    }
    int n = threadIdx.x;
    size_t mb = (size_t)blockIdx.x * HID * HID;
    int k0 = blockIdx.y * 32;
    for (int k = k0; k < k0 + 32; k++) {
        float v = src[(size_t)k * HID + n];
        __nv_bfloat16 h = __float2bfloat16(v);
        float lo = v - __bfloat162float(h);
        g_Whi[mb + (size_t)n * HID + k] = h;
        g_Wlo[mb + (size_t)n * HID + k] = __float2bfloat16(lo);
    }
}

// ---------------- elementwise / structural kernels (proven) ----------------
__global__ void k_M0() {
    size_t o = (size_t)blockIdx.x * HID + threadIdx.x;
    g_M0[o] = sigf(g_Pz[o]) * tanhf(g_Ph[o]);
}

__global__ void k_bu_leaf(const int* __restrict__ wid, float* __restrict__ out) {
    int p = blockIdx.x, j = threadIdx.x;
    int tree = p >> 3, q = p & 7;
    int pl = 7 + q;
    int parent = tree * NT + pl;
    int c0 = 2 * pl + 1;
    int child0 = tree * NT + c0;
    int w0 = wid[child0], w1 = wid[child0 + 1];
    float pr = g_Pr[(size_t)wid[parent] * HID + j];
    float m0 = g_M0[(size_t)w0 * HID + j];
    float m1 = g_M0[(size_t)w1 * HID + j];
    float r0 = sigf(pr + g_MU0[(size_t)w0 * HID + j]);
    float r1 = sigf(pr + g_MU0[(size_t)w1 * HID + j]);
    size_t e0 = (size_t)(tree * NE_TREE + c0 - 1) * HID + j;
    out[e0]       = m0;
    out[e0 + HID] = m1;
    size_t po = (size_t)parent * HID + j;
    g_s[po]  = m0 + m1;
    g_rm[po] = m0 * r0 + m1 * r1;
}

__global__ void k_bu_M(int L, int base, float* __restrict__ out) {
    int e = blockIdx.x, j = threadIdx.x;
    int tree = e >> L, jj = e & ((1 << L) - 1);
    int child = tree * NT + base + jj;
    size_t eo = (size_t)e * HID + j;
    float z = g_T1[eo], h = g_T2[eo];
    float s = g_s[(size_t)child * HID + j];
    out[(size_t)(tree * NE_TREE + base - 1 + jj) * HID + j] = (1.0f - z) * s + z * h;
}

__global__ void k_bu_reduce(int d, int base, const float* __restrict__ out) {
    int p = blockIdx.x, j = threadIdx.x;
    int tree = p >> d, q = p & ((1 << d) - 1);
    int pl = (1 << d) - 1 + q;
    int parent = tree * NT + pl;
    int e0row = tree * (1 << (d + 1)) + 2 * q;
    size_t eid0 = (size_t)(tree * NE_TREE + base - 1 + 2 * q) * HID + j;
    float m0 = out[eid0], m1 = out[eid0 + HID];
    float r0 = g_T1[(size_t)e0row * HID + j];
    float r1 = g_T1[(size_t)(e0row + 1) * HID + j];
    size_t po = (size_t)parent * HID + j;
    g_s[po]  = m0 + m1;
    g_rm[po] = m0 * r0 + m1 * r1;
}

__global__ void k_td_root(const int* __restrict__ wid, float* __restrict__ out) {
    int tree = blockIdx.x, j = threadIdx.x;
    int wr = wid[tree * NT];
    float m  = g_M0 [(size_t)wr * HID + j];
    float mu = g_MU0[(size_t)wr * HID + j];
    #pragma unroll
    for (int c = 1; c <= 2; c++) {
        int child = tree * NT + c;
        float r = sigf(g_Pr[(size_t)wid[child] * HID + j] + mu);
        size_t co = (size_t)child * HID + j;
        g_s[co]  = m;
        g_rm[co] = m * r;
        out[(size_t)(NE_HALF + tree * NE_TREE + c - 1) * HID + j] = m;
    }
}

__global__ void k_td_M(int d, float* __restrict__ out) {
    int p = blockIdx.x, j = threadIdx.x;
    int tree = p >> d, q = p & ((1 << d) - 1);
    int pl = (1 << d) - 1 + q;
    int parent = tree * NT + pl;
    size_t po = (size_t)p * HID + j;
    float z = g_T1[po], h = g_T2[po];
    float s = g_s[(size_t)parent * HID + j];
    float m = (1.0f - z) * s + z * h;
    g_M[po] = m;
    size_t eid0 = (size_t)(NE_HALF + tree * NE_TREE + 2 * pl) * HID + j;
    out[eid0]       = m;
    out[eid0 + HID] = m;
}

__global__ void k_td_child(int d, const int* __restrict__ wid) {
    int cr = blockIdx.x, j = threadIdx.x;
    int p = cr >> 1, which = cr & 1;
    int tree = p >> d, q = p & ((1 << d) - 1);
    int pl = (1 << d) - 1 + q;
    int child = tree * NT + 2 * pl + 1 + which;
    size_t po = (size_t)p * HID + j;
    float m = g_M[po];
    float r = sigf(g_Pr[(size_t)wid[child] * HID + j] + g_T3[po]);
    size_t co = (size_t)child * HID + j;
    g_s[co]  = m;
    g_rm[co] = m * r;
}

// ---------------- host ----------------
static inline void launch_jobs(const GJob* js, int nz,
                               int aL, int aRS, int aBase, int R,
                               const int* wid, int pMode, int pL, int pRS, int pBase)
{
    dim3 g((R + 127) / 128, 2, nz);
    gemm_mma<<<g, 256, SMEM_TOT>>>(
        js[0], (nz > 1) ? js[1] : js[0], (nz > 2) ? js[2] : js[0], (nz > 3) ? js[3] : js[0],
        aL, aRS, aBase, R, wid, pMode, pL, pRS, pBase);
}

extern "C" void kernel_launch(void* const* d_in, const int* in_sizes, int n_in,
                              void* d_out, int out_size)
{
    const int*   wid = (const int*)  d_in[0];
    const float* emb = (const float*)d_in[1];
    const float* Wz  = (const float*)d_in[2];
    const float* bz  = (const float*)d_in[3];
    const float* Wh  = (const float*)d_in[4];
    const float* bh  = (const float*)d_in[5];
    const float* Wr  = (const float*)d_in[6];
    const float* Ur  = (const float*)d_in[7];
    const float* bu  = (const float*)d_in[8];
    const float* Wf  = (const float*)d_in[9];
    const float* bf  = (const float*)d_in[10];
    float* out = (float*)d_out;

    float *p_s, *p_rm, *p_T1, *p_T2, *p_T3, *p_M;
    float *p_Pz, *p_Ph, *p_Pr, *p_Pf, *p_M0, *p_MU0;
    cudaGetSymbolAddress((void**)&p_s,   g_s);
    cudaGetSymbolAddress((void**)&p_rm,  g_rm);
    cudaGetSymbolAddress((void**)&p_T1,  g_T1);
    cudaGetSymbolAddress((void**)&p_T2,  g_T2);
    cudaGetSymbolAddress((void**)&p_T3,  g_T3);
    cudaGetSymbolAddress((void**)&p_M,   g_M);
    cudaGetSymbolAddress((void**)&p_Pz,  g_Pz);
    cudaGetSymbolAddress((void**)&p_Ph,  g_Ph);
    cudaGetSymbolAddress((void**)&p_Pr,  g_Pr);
    cudaGetSymbolAddress((void**)&p_Pf,  g_Pf);
    cudaGetSymbolAddress((void**)&p_M0,  g_M0);
    cudaGetSymbolAddress((void**)&p_MU0, g_MU0);

    cudaFuncSetAttribute(gemm_mma, cudaFuncAttributeMaxDynamicSharedMemorySize, SMEM_TOT);

    // ---- weight prep (transpose + bf16 split) ----
    k_prepw<<<dim3(8, 8), 256>>>(Wz, Wh, Wr, Ur, Wf);

    // ---- vocab tables: 4 GEMMs in ONE launch (grid.z=4) ----
    {
        GJob js[4] = {
            { emb, p_Pz, nullptr, bz, 0, 0 },
            { emb, p_Ph, nullptr, bh, 2, 0 },
            { emb, p_Pr, nullptr, bu, 4, 0 },
            { emb, p_Pf, nullptr, bf, 6, 0 },
        };
        launch_jobs(js, 4, 0, 1, 0, VOCAB, wid, 0, 0, 0, 0);
    }
    k_M0<<<VOCAB, HID>>>();
    {
        GJob js[1] = { { p_M0, p_MU0, nullptr, nullptr, 5, 0 } };
        launch_jobs(js, 1, 0, 1, 0, VOCAB, wid, 0, 0, 0, 0);
    }

    // ---- bottom-up pass ----
    k_bu_leaf<<<NTREES * 8, HID>>>(wid, out);
    for (int d = 2; d >= 0; d--) {
        int L = d + 1;
        int base = (1 << (d + 1)) - 1;
        int E = NTREES << (d + 1);
        // Z and H in one launch (independent, same row gather)
        GJob zh[2] = {
            { p_s,  p_T1, p_Pz, nullptr, 1, 1 },   // Z = sigmoid(Pz + s@Wzs)
            { p_rm, p_T2, p_Ph, nullptr, 3, 2 },   // H = tanh(Ph + rm@Whs)
        };
        launch_jobs(zh, 2, L, NT, base, E, wid, 1, L, NT, base);
        k_bu_M<<<E, HID>>>(L, base, out);
        // R = sigmoid(Pr[wid_parent] + M @ Ur)
        GJob jr[1] = { { out, p_T1, p_Pr, nullptr, 5, 1 } };
        launch_jobs(jr, 1, L, NE_TREE, base - 1, E, wid, 2, L, NT, base);
        k_bu_reduce<<<E / 2, HID>>>(d, base, out);
    }

    // ---- h_root = relu(Pf[wid_root] + s_root @ Wfs) ----
    {
        GJob jf[1] = { { p_s, out + (size_t)2 * NE_HALF * HID, p_Pf, nullptr, 7, 3 } };
        launch_jobs(jf, 1, 0, NT, 0, NTREES, wid, 1, 0, NT, 0);
    }

    // ---- top-down pass ----
    k_td_root<<<NTREES, HID>>>(wid, out);
    for (int d = 1; d <= 3; d++) {
        int pb = (1 << d) - 1;
        int Pn = NTREES << d;
        GJob zh[2] = {
            { p_s,  p_T1, p_Pz, nullptr, 1, 1 },
            { p_rm, p_T2, p_Ph, nullptr, 3, 2 },
        };
        launch_jobs(zh, 2, d, NT, pb, Pn, wid, 1, d, NT, pb);
        k_td_M<<<Pn, HID>>>(d, out);
        GJob ju[1] = { { p_M, p_T3, nullptr, nullptr, 5, 0 } };
        launch_jobs(ju, 1, 0, 1, 0, Pn, wid, 0, 0, 0, 0);
        k_td_child<<<2 * Pn, HID>>>(d, wid);
    }
}